// round 3
// baseline (speedup 1.0000x reference)
#include <cuda_runtime.h>
#include <cuda_bf16.h>
#include <math.h>

#define Bz 4
#define Cc 64
#define Hh 128
#define Ww 128
#define HW (Hh*Ww)
#define KK 9
#define Ee 64
#define CK 576

// ---------------- scratch (device globals; no allocation) ----------------
__device__ float g_xe  [(size_t)Bz*Cc*HW];   // encoded x
__device__ float g_t1  [(size_t)Bz*Cc*HW];   // dw output / out0
__device__ float g_bufA[(size_t)Bz*Ee*HW];
__device__ float g_bufB[(size_t)Bz*Ee*HW];
__device__ float g_off [(size_t)Bz*2*KK*HW];
__device__ float g_xb  [(size_t)Bz*CK*HW];
__device__ float g_dct [(size_t)Bz*CK*HW];
__device__ float g_y1  [(size_t)Bz*CK*HW];
__device__ float g_y2  [(size_t)Bz*CK*HW];

// ---------------- depthwise 7x7 pad 3 (per channel) ----------------
__global__ void dw7_kernel(const float* __restrict__ in, const float* __restrict__ w,
                           float* __restrict__ out) {
    int tx = threadIdx.x;          // w
    int h  = blockIdx.x;
    int bc = blockIdx.y;           // b*C + c
    int c  = bc & 63;
    const float* wp = w + c*49;
    const float* ip = in + (size_t)bc*HW;
    float acc = 0.f;
    #pragma unroll
    for (int kh = 0; kh < 7; kh++) {
        int y = h + kh - 3;
        if (y < 0 || y >= Hh) continue;
        #pragma unroll
        for (int kw = 0; kw < 7; kw++) {
            int x = tx + kw - 3;
            if (x < 0 || x >= Ww) continue;
            acc += wp[kh*7+kw] * ip[y*Ww + x];
        }
    }
    out[(size_t)bc*HW + h*Ww + tx] = acc;
}

// ---------------- convnext pointwise MLP + residual ----------------
// out = xres + pw2 @ relu(pw1 @ t)    (pw1: 128x64, pw2: 64x128)
__global__ __launch_bounds__(256) void convnext_pw_kernel(
        const float* __restrict__ xres, const float* __restrict__ t,
        const float* __restrict__ pw1,  const float* __restrict__ pw2,
        float* __restrict__ out) {
    __shared__ float s1[64][64];
    __shared__ float s2[64][64];
    int tid = threadIdx.x;
    size_t g = (size_t)blockIdx.x * 256 + tid;
    int b = (int)(g / HW);
    int p = (int)(g % HW);
    const float* tp = t + (size_t)b*Cc*HW + p;
    float xin[64];
    #pragma unroll
    for (int i = 0; i < 64; i++) xin[i] = tp[(size_t)i*HW];
    float acc[64];
    #pragma unroll
    for (int i = 0; i < 64; i++) acc[i] = 0.f;

    for (int chunk = 0; chunk < 2; chunk++) {
        __syncthreads();
        for (int i = tid; i < 4096; i += 256) (&s1[0][0])[i] = pw1[chunk*4096 + i];
        for (int i = tid; i < 4096; i += 256) {
            int c = i >> 6, mm = i & 63;
            s2[c][mm] = pw2[c*128 + chunk*64 + mm];
        }
        __syncthreads();
        for (int mm = 0; mm < 64; mm += 4) {
            float hv[4];
            #pragma unroll
            for (int j = 0; j < 4; j++) {
                float s = 0.f;
                #pragma unroll
                for (int i = 0; i < 64; i += 4) {
                    float4 wv = *(const float4*)&s1[mm+j][i];
                    s += wv.x*xin[i] + wv.y*xin[i+1] + wv.z*xin[i+2] + wv.w*xin[i+3];
                }
                hv[j] = fmaxf(s, 0.f);
            }
            #pragma unroll
            for (int c = 0; c < 64; c++) {
                float4 wv = *(const float4*)&s2[c][mm];
                acc[c] += wv.x*hv[0] + wv.y*hv[1] + wv.z*hv[2] + wv.w*hv[3];
            }
        }
    }
    const float* xp = xres + (size_t)b*Cc*HW + p;
    float* op = out + (size_t)b*Cc*HW + p;
    #pragma unroll
    for (int c = 0; c < 64; c++) op[(size_t)c*HW] = xp[(size_t)c*HW] + acc[c];
}

// ---------------- 1x1 conv 64->64 + bias + leaky(0.1) ----------------
__global__ __launch_bounds__(256) void conv1x1_64_kernel(
        const float* __restrict__ in, const float* __restrict__ wgt,
        const float* __restrict__ bias, float* __restrict__ out) {
    __shared__ float sw[4096];
    int tid = threadIdx.x;
    for (int i = tid; i < 4096; i += 256) sw[i] = wgt[i];
    __syncthreads();
    size_t g = (size_t)blockIdx.x * 256 + tid;
    int b = (int)(g / HW);
    int p = (int)(g % HW);
    const float* ip = in + (size_t)b*64*HW + p;
    float x[64];
    #pragma unroll
    for (int i = 0; i < 64; i++) x[i] = ip[(size_t)i*HW];
    float* op = out + (size_t)b*64*HW + p;
    for (int co = 0; co < 64; co++) {
        float s = bias[co];
        #pragma unroll
        for (int i = 0; i < 64; i += 4) {
            float4 wv = *(const float4*)&sw[co*64 + i];
            s += wv.x*x[i] + wv.y*x[i+1] + wv.z*x[i+2] + wv.w*x[i+3];
        }
        s = (s > 0.f) ? s : 0.1f*s;
        op[(size_t)co*HW] = s;
    }
}

// ---------------- 3x3 conv 64->64 pad1 + bias + leaky(0.1) ----------------
__global__ __launch_bounds__(128) void conv3x3_kernel(
        const float* __restrict__ in, const float* __restrict__ wgt,
        const float* __restrict__ bias, float* __restrict__ out) {
    int tx = threadIdx.x;        // w
    int h  = blockIdx.x;
    int b  = blockIdx.y;
    __shared__ float sIn[3][Ww];
    __shared__ float sW[576];    // sW[k*64 + co]
    float acc[64];
    #pragma unroll
    for (int i = 0; i < 64; i++) acc[i] = 0.f;
    const float* inb = in + (size_t)b*64*HW;

    for (int ci = 0; ci < 64; ci++) {
        __syncthreads();
        const float* ip = inb + (size_t)ci*HW;
        #pragma unroll
        for (int r = 0; r < 3; r++) {
            int y = h + r - 1;
            sIn[r][tx] = (y >= 0 && y < Hh) ? ip[y*Ww + tx] : 0.f;
        }
        for (int i = tx; i < 576; i += 128)
            sW[i] = wgt[(size_t)(i & 63)*576 + ci*9 + (i >> 6)];
        __syncthreads();
        float a[9];
        #pragma unroll
        for (int kh = 0; kh < 3; kh++) {
            a[kh*3+0] = (tx >= 1)      ? sIn[kh][tx-1] : 0.f;
            a[kh*3+1] =                   sIn[kh][tx];
            a[kh*3+2] = (tx < Ww-1)    ? sIn[kh][tx+1] : 0.f;
        }
        #pragma unroll
        for (int k = 0; k < 9; k++) {
            float av = a[k];
            #pragma unroll
            for (int c4 = 0; c4 < 16; c4++) {
                float4 wv = *(const float4*)&sW[k*64 + c4*4];
                acc[c4*4+0] += wv.x*av;
                acc[c4*4+1] += wv.y*av;
                acc[c4*4+2] += wv.z*av;
                acc[c4*4+3] += wv.w*av;
            }
        }
    }
    float* op = out + (size_t)b*64*HW + h*Ww + tx;
    #pragma unroll
    for (int co = 0; co < 64; co++) {
        float v = acc[co] + bias[co];
        v = (v > 0.f) ? v : 0.1f*v;
        op[(size_t)co*HW] = v;
    }
}

// ---------------- 1x1 conv 64->18 + bias, offsets = 8*tanh ----------------
__global__ __launch_bounds__(256) void off_final_kernel(
        const float* __restrict__ in, const float* __restrict__ wgt,
        const float* __restrict__ bias, float* __restrict__ out) {
    __shared__ float sw[18*64];
    int tid = threadIdx.x;
    for (int i = tid; i < 18*64; i += 256) sw[i] = wgt[i];
    __syncthreads();
    size_t g = (size_t)blockIdx.x * 256 + tid;
    int b = (int)(g / HW);
    int p = (int)(g % HW);
    const float* ip = in + (size_t)b*64*HW + p;
    float x[64];
    #pragma unroll
    for (int i = 0; i < 64; i++) x[i] = ip[(size_t)i*HW];
    float* op = out + (size_t)b*18*HW + p;
    for (int co = 0; co < 18; co++) {
        float s = bias[co];
        #pragma unroll
        for (int i = 0; i < 64; i += 4) {
            float4 wv = *(const float4*)&sw[co*64 + i];
            s += wv.x*x[i] + wv.y*x[i+1] + wv.z*x[i+2] + wv.w*x[i+3];
        }
        op[(size_t)co*HW] = 8.f * tanhf(s);
    }
}

// ---------------- deformable bilinear gather ----------------
// xb[b][c*9+k][h][w] = bilinear(x[b][c], h + (k/3-1) + dy, w + (k%3-1) + dx)
__global__ __launch_bounds__(128) void deform_kernel(
        const float* __restrict__ x, const float* __restrict__ off,
        float* __restrict__ xb) {
    int tx = threadIdx.x;   // w
    int h  = blockIdx.x;
    int k  = blockIdx.y;
    int b  = blockIdx.z;
    int pix = h*Ww + tx;
    const float* ob = off + (size_t)b*18*HW;
    float dy = ob[(size_t)(2*k)*HW + pix];
    float dx = ob[(size_t)(2*k+1)*HW + pix];
    float py = (float)h + (float)(k/3 - 1) + dy;
    float px = (float)tx + (float)(k%3 - 1) + dx;
    float y0f = floorf(py), x0f = floorf(px);
    int y0 = (int)y0f, x0 = (int)x0f;
    float wy1 = py - y0f, wy0 = 1.f - wy1;
    float wx1 = px - x0f, wx0 = 1.f - wx1;
    bool vy0 = (y0 >= 0 && y0 < Hh), vy1 = (y0+1 >= 0 && y0+1 < Hh);
    bool vx0 = (x0 >= 0 && x0 < Ww), vx1 = (x0+1 >= 0 && x0+1 < Ww);
    int yc0 = min(max(y0, 0), Hh-1),   yc1 = min(max(y0+1, 0), Hh-1);
    int xc0 = min(max(x0, 0), Ww-1),   xc1 = min(max(x0+1, 0), Ww-1);
    float w00 = (vy0 && vx0) ? wy0*wx0 : 0.f;
    float w01 = (vy0 && vx1) ? wy0*wx1 : 0.f;
    float w10 = (vy1 && vx0) ? wy1*wx0 : 0.f;
    float w11 = (vy1 && vx1) ? wy1*wx1 : 0.f;
    int i00 = yc0*Ww + xc0, i01 = yc0*Ww + xc1;
    int i10 = yc1*Ww + xc0, i11 = yc1*Ww + xc1;
    const float* xbase = x + (size_t)b*Cc*HW;
    float* op = xb + ((size_t)b*CK + k)*HW + pix;
    #pragma unroll 4
    for (int c = 0; c < 64; c++) {
        const float* xp = xbase + (size_t)c*HW;
        float v = w00*xp[i00] + w01*xp[i01] + w10*xp[i10] + w11*xp[i11];
        op[(size_t)c*9*HW] = v;
    }
}

// ---------------- grouped 9x9 1x1 conv (per channel c), optional elemwise mul ----------------
// out[b][c*9+j] = sum_k wgt[(c*9+j)*9+k] * (in[b][c*9+k] * (in2? in2 : 1))
__global__ __launch_bounds__(128) void grouped9_kernel(
        const float* __restrict__ in, const float* __restrict__ in2,
        const float* __restrict__ wgt, float* __restrict__ out) {
    int tx = threadIdx.x;
    int h  = blockIdx.x;
    int bc = blockIdx.y;        // b*64 + c
    int c  = bc & 63;
    size_t base = ((size_t)(bc >> 6)*CK + c*9)*HW + h*Ww + tx;
    float v[9];
    #pragma unroll
    for (int k = 0; k < 9; k++) {
        float t = in[base + (size_t)k*HW];
        if (in2) t *= in2[base + (size_t)k*HW];
        v[k] = t;
    }
    const float* wp = wgt + c*81;
    #pragma unroll
    for (int j = 0; j < 9; j++) {
        float s = 0.f;
        #pragma unroll
        for (int k = 0; k < 9; k++) s += __ldg(&wp[j*9+k]) * v[k];
        out[base + (size_t)j*HW] = s;
    }
}

// ---------------- depthwise 3x3 pad1 on CK channels + activation ----------------
// act: 0 = relu, 1 = sigmoid
__global__ __launch_bounds__(128) void dw3ck_kernel(
        const float* __restrict__ in, const float* __restrict__ wgt,
        float* __restrict__ out, int act) {
    int tx = threadIdx.x;
    int h  = blockIdx.x;
    int bc = blockIdx.y;        // b*576 + cc
    int cc = bc % CK;
    const float* ip = in + (size_t)bc*HW;
    const float* wp = wgt + cc*9;
    float acc = 0.f;
    #pragma unroll
    for (int kh = 0; kh < 3; kh++) {
        int y = h + kh - 1;
        if (y < 0 || y >= Hh) continue;
        #pragma unroll
        for (int kw = 0; kw < 3; kw++) {
            int xw = tx + kw - 1;
            if (xw < 0 || xw >= Ww) continue;
            acc += __ldg(&wp[kh*3+kw]) * ip[y*Ww + xw];
        }
    }
    if (act == 0) acc = fmaxf(acc, 0.f);
    else          acc = 1.f / (1.f + expf(-acc));
    out[(size_t)bc*HW + h*Ww + tx] = acc;
}

// ---------------- fp32 GEMM for 1x1 convs: Y[b][m][n] = sum_k A[m][k]*X[b][k][n] ----------------
#define BM 64
#define BN 128
#define BK 16
__global__ __launch_bounds__(256) void gemm_kernel(
        const float* __restrict__ A, const float* __restrict__ X,
        float* __restrict__ Y, int M, int Kd) {
    int b  = blockIdx.z;
    const float* Bb = X + (size_t)b*Kd*HW;
    float*       Cb = Y + (size_t)b*M*HW;
    int m0 = blockIdx.y * BM;
    int n0 = blockIdx.x * BN;
    __shared__ float As[BM][20];     // padded row (20 floats) keeps float4 alignment, kills conflicts
    __shared__ float Bs[BK][BN];
    int tid = threadIdx.x;
    int tx = tid & 15, ty = tid >> 4;
    float acc[4][8];
    #pragma unroll
    for (int i = 0; i < 4; i++)
        #pragma unroll
        for (int j = 0; j < 8; j++) acc[i][j] = 0.f;

    int am = tid >> 2;            // 0..63
    int ak = (tid & 3) * 4;       // 0,4,8,12
    int bk = tid >> 4;            // 0..15
    int bn = (tid & 15) * 8;      // 0..120

    for (int k0 = 0; k0 < Kd; k0 += BK) {
        float4 av  = *(const float4*)(A  + (size_t)(m0+am)*Kd + k0 + ak);
        float4 bv0 = *(const float4*)(Bb + (size_t)(k0+bk)*HW + n0 + bn);
        float4 bv1 = *(const float4*)(Bb + (size_t)(k0+bk)*HW + n0 + bn + 4);
        __syncthreads();
        *(float4*)&As[am][ak]   = av;
        *(float4*)&Bs[bk][bn]   = bv0;
        *(float4*)&Bs[bk][bn+4] = bv1;
        __syncthreads();
        #pragma unroll
        for (int k = 0; k < BK; k++) {
            float4 b0 = *(const float4*)&Bs[k][tx*8];
            float4 b1 = *(const float4*)&Bs[k][tx*8+4];
            float br[8] = {b0.x,b0.y,b0.z,b0.w,b1.x,b1.y,b1.z,b1.w};
            #pragma unroll
            for (int i = 0; i < 4; i++) {
                float ar = As[ty*4+i][k];
                #pragma unroll
                for (int j = 0; j < 8; j++) acc[i][j] += ar * br[j];
            }
        }
    }
    #pragma unroll
    for (int i = 0; i < 4; i++) {
        float* cp = Cb + (size_t)(m0 + ty*4 + i)*HW + n0 + tx*8;
        float4 o0 = make_float4(acc[i][0], acc[i][1], acc[i][2], acc[i][3]);
        float4 o1 = make_float4(acc[i][4], acc[i][5], acc[i][6], acc[i][7]);
        *(float4*)(cp)     = o0;
        *(float4*)(cp + 4) = o1;
    }
}

// ---------------- host orchestration ----------------
extern "C" void kernel_launch(void* const* d_in, const int* in_sizes, int n_in,
                              void* d_out, int out_size) {
    const float* x       = (const float*)d_in[0];
    const float* enc_dw  = (const float*)d_in[1];
    const float* enc_pw1 = (const float*)d_in[2];
    const float* enc_pw2 = (const float*)d_in[3];
    const float* dec_dw  = (const float*)d_in[4];
    const float* dec_pw1 = (const float*)d_in[5];
    const float* dec_pw2 = (const float*)d_in[6];
    const float* off_w1  = (const float*)d_in[7];
    const float* off_b1  = (const float*)d_in[8];
    const float* off_w2  = (const float*)d_in[9];
    const float* off_b2  = (const float*)d_in[10];
    const float* off_w3  = (const float*)d_in[11];
    const float* off_b3  = (const float*)d_in[12];
    const float* off_w4  = (const float*)d_in[13];
    const float* off_b4  = (const float*)d_in[14];
    const float* off_w5  = (const float*)d_in[15];
    const float* off_b5  = (const float*)d_in[16];
    const float* off_w6  = (const float*)d_in[17];
    const float* off_b6  = (const float*)d_in[18];
    const float* dct_w   = (const float*)d_in[19];
    const float* wie_w1  = (const float*)d_in[20];
    const float* wie_w2  = (const float*)d_in[21];
    const float* wie_w3  = (const float*)d_in[22];
    const float* wie_w4  = (const float*)d_in[23];
    const float* wie_w5  = (const float*)d_in[24];
    const float* wie_w6  = (const float*)d_in[25];
    const float* inv_w1  = (const float*)d_in[26];
    const float* inv_w2  = (const float*)d_in[27];

    float *xe, *t1, *bufA, *bufB, *offs, *xb, *dct, *y1, *y2;
    cudaGetSymbolAddress((void**)&xe,   g_xe);
    cudaGetSymbolAddress((void**)&t1,   g_t1);
    cudaGetSymbolAddress((void**)&bufA, g_bufA);
    cudaGetSymbolAddress((void**)&bufB, g_bufB);
    cudaGetSymbolAddress((void**)&offs, g_off);
    cudaGetSymbolAddress((void**)&xb,   g_xb);
    cudaGetSymbolAddress((void**)&dct,  g_dct);
    cudaGetSymbolAddress((void**)&y1,   g_y1);
    cudaGetSymbolAddress((void**)&y2,   g_y2);

    const int pixBlocks = (Bz*HW) / 256;          // 256

    // ---- encoder convnext ----
    dw7_kernel<<<dim3(Hh, Bz*Cc), Ww>>>(x, enc_dw, t1);
    convnext_pw_kernel<<<pixBlocks, 256>>>(x, t1, enc_pw1, enc_pw2, xe);

    // ---- offset CNN ----
    conv1x1_64_kernel<<<pixBlocks, 256>>>(xe, off_w1, off_b1, bufA);
    conv3x3_kernel<<<dim3(Hh, Bz), Ww>>>(bufA, off_w2, off_b2, bufB);
    conv3x3_kernel<<<dim3(Hh, Bz), Ww>>>(bufB, off_w3, off_b3, bufA);
    conv3x3_kernel<<<dim3(Hh, Bz), Ww>>>(bufA, off_w4, off_b4, bufB);
    conv3x3_kernel<<<dim3(Hh, Bz), Ww>>>(bufB, off_w5, off_b5, bufA);
    off_final_kernel<<<pixBlocks, 256>>>(bufA, off_w6, off_b6, offs);

    // ---- deformable neighbourhood ----
    deform_kernel<<<dim3(Hh, KK, Bz), Ww>>>(xe, offs, xb);

    // ---- dct branch (grouped 9x9) ----
    grouped9_kernel<<<dim3(Hh, Bz*Cc), Ww>>>(xb, nullptr, dct_w, dct);

    // ---- wiener branch: three 576x576 GEMMs + depthwise 3x3 ----
    dim3 ggrid(HW/BN, CK/BM, Bz);
    gemm_kernel<<<ggrid, 256>>>(wie_w1, xb, y1, CK, CK);
    dw3ck_kernel<<<dim3(Hh, Bz*CK), Ww>>>(y1, wie_w2, y2, 0);
    gemm_kernel<<<ggrid, 256>>>(wie_w3, y2, y1, CK, CK);
    dw3ck_kernel<<<dim3(Hh, Bz*CK), Ww>>>(y1, wie_w4, y2, 0);
    gemm_kernel<<<ggrid, 256>>>(wie_w5, y2, y1, CK, CK);
    dw3ck_kernel<<<dim3(Hh, Bz*CK), Ww>>>(y1, wie_w6, y2, 1);   // sigmoid -> wiener

    // ---- inverse: (wiener*dct) -> grouped 9x9 -> 576->64 GEMM ----
    grouped9_kernel<<<dim3(Hh, Bz*Cc), Ww>>>(y2, dct, inv_w1, y1);
    gemm_kernel<<<dim3(HW/BN, 1, Bz), 256>>>(inv_w2, y1, t1, 64, CK);

    // ---- decoder convnext -> d_out ----
    dw7_kernel<<<dim3(Hh, Bz*Cc), Ww>>>(t1, dec_dw, bufA);
    convnext_pw_kernel<<<pixBlocks, 256>>>(t1, bufA, dec_pw1, dec_pw2, (float*)d_out);
}

// round 7
// speedup vs baseline: 1.5408x; 1.5408x over previous
#include <cuda_runtime.h>
#include <cuda_bf16.h>
#include <math.h>
#include <stdint.h>

#define Bz 4
#define Cc 64
#define Hh 128
#define Ww 128
#define HW (Hh*Ww)
#define KK 9
#define Ee 64
#define CK 576

// ---------------- scratch (device globals; no allocation) ----------------
__device__ float g_xe  [(size_t)Bz*Cc*HW];   // encoded x
__device__ float g_t1  [(size_t)Bz*Cc*HW];   // dw output / out0
__device__ float g_bufA[(size_t)Bz*Ee*HW];
__device__ float g_bufB[(size_t)Bz*Ee*HW];
__device__ float g_off [(size_t)Bz*2*KK*HW];
__device__ float g_xb  [(size_t)Bz*CK*HW];
__device__ float g_dct [(size_t)Bz*CK*HW];
__device__ float g_y1  [(size_t)Bz*CK*HW];
__device__ float g_y2  [(size_t)Bz*CK*HW];

// ================= tf32 helpers (legacy mma.sync path; valid on compute_103) =================
__device__ __forceinline__ float tf32_rnd(float v) {
    uint32_t u;
    asm("cvt.rna.tf32.f32 %0, %1;" : "=r"(u) : "f"(v));
    return __uint_as_float(u);
}

__device__ __forceinline__ void mma_tf32(float* c, const uint32_t* a, const uint32_t* b) {
    asm volatile(
        "mma.sync.aligned.m16n8k8.row.col.f32.tf32.tf32.f32 "
        "{%0,%1,%2,%3}, {%4,%5,%6,%7}, {%8,%9}, {%0,%1,%2,%3};"
        : "+f"(c[0]), "+f"(c[1]), "+f"(c[2]), "+f"(c[3])
        : "r"(a[0]), "r"(a[1]), "r"(a[2]), "r"(a[3]), "r"(b[0]), "r"(b[1]));
}

// ================= 3xTF32 GEMM via mma.sync =================
// Y[b][m][n] = sum_k A[m][k] * X[b][k][n];  A: MxK row-major, X: [K][HW] per batch.
#define BMt 128
#define BNt 128
#define KCt 32
#define AS_STRIDE 36
#define BS_STRIDE 132
#define OFF_AH 0
#define OFF_AL (BMt*AS_STRIDE)                           // 4608
#define OFF_BH (2*BMt*AS_STRIDE)                         // 9216
#define OFF_BL (2*BMt*AS_STRIDE + KCt*BS_STRIDE)         // 13440
#define GEMM_SMEM ((2*BMt*AS_STRIDE + 2*KCt*BS_STRIDE)*4)  // 70656 bytes

__global__ __launch_bounds__(256, 2) void gemm_mma_kernel(
        const float* __restrict__ A, const float* __restrict__ X,
        float* __restrict__ Y, int M, int Kd) {
    extern __shared__ float smf[];
    float* AH = smf + OFF_AH;
    float* AL = smf + OFF_AL;
    float* BH = smf + OFF_BH;
    float* BL = smf + OFF_BL;

    int tid  = threadIdx.x;
    int lane = tid & 31;
    int wid  = tid >> 5;
    int wm = wid >> 2;          // 0..1  -> m offset wm*64
    int wn = wid & 3;           // 0..3  -> n offset wn*32
    int row4 = lane >> 2;       // 0..7
    int col4 = lane & 3;        // 0..3

    int b  = blockIdx.z;
    int n0 = blockIdx.x * BNt;
    int m0 = blockIdx.y * BMt;
    const float* Bb = X + (size_t)b*Kd*HW;
    float*       Cb = Y + (size_t)b*M*HW;

    float acc[4][4][4];
    #pragma unroll
    for (int i = 0; i < 4; i++)
        #pragma unroll
        for (int j = 0; j < 4; j++)
            #pragma unroll
            for (int r = 0; r < 4; r++) acc[i][j][r] = 0.f;

    for (int k0 = 0; k0 < Kd; k0 += KCt) {
        __syncthreads();   // previous compute finished reading smem

        // ---- stage A (128x32) hi/lo ----
        #pragma unroll
        for (int j = 0; j < 4; j++) {
            int f = tid + j*256;
            int m = f >> 3, q = f & 7;
            float4 v = (m0 + m < M)
                ? *(const float4*)(A + (size_t)(m0+m)*Kd + k0 + q*4)
                : make_float4(0.f,0.f,0.f,0.f);
            float4 h, l;
            h.x = tf32_rnd(v.x); l.x = tf32_rnd(v.x - h.x);
            h.y = tf32_rnd(v.y); l.y = tf32_rnd(v.y - h.y);
            h.z = tf32_rnd(v.z); l.z = tf32_rnd(v.z - h.z);
            h.w = tf32_rnd(v.w); l.w = tf32_rnd(v.w - h.w);
            *(float4*)(AH + m*AS_STRIDE + q*4) = h;
            *(float4*)(AL + m*AS_STRIDE + q*4) = l;
        }
        // ---- stage B (32x128) hi/lo ----
        #pragma unroll
        for (int j = 0; j < 4; j++) {
            int f = tid + j*256;
            int k = f >> 5, q = f & 31;
            float4 v = *(const float4*)(Bb + (size_t)(k0+k)*HW + n0 + q*4);
            float4 h, l;
            h.x = tf32_rnd(v.x); l.x = tf32_rnd(v.x - h.x);
            h.y = tf32_rnd(v.y); l.y = tf32_rnd(v.y - h.y);
            h.z = tf32_rnd(v.z); l.z = tf32_rnd(v.z - h.z);
            h.w = tf32_rnd(v.w); l.w = tf32_rnd(v.w - h.w);
            *(float4*)(BH + k*BS_STRIDE + q*4) = h;
            *(float4*)(BL + k*BS_STRIDE + q*4) = l;
        }
        __syncthreads();

        // ---- compute: 4 k-steps of 8 ----
        #pragma unroll
        for (int ks = 0; ks < 4; ks++) {
            int k8 = ks*8;
            uint32_t ah[4][4], al[4][4];
            #pragma unroll
            for (int mf = 0; mf < 4; mf++) {
                int base = (wm*64 + mf*16 + row4)*AS_STRIDE + k8 + col4;
                ah[mf][0] = __float_as_uint(AH[base]);
                ah[mf][1] = __float_as_uint(AH[base + 8*AS_STRIDE]);
                ah[mf][2] = __float_as_uint(AH[base + 4]);
                ah[mf][3] = __float_as_uint(AH[base + 8*AS_STRIDE + 4]);
                al[mf][0] = __float_as_uint(AL[base]);
                al[mf][1] = __float_as_uint(AL[base + 8*AS_STRIDE]);
                al[mf][2] = __float_as_uint(AL[base + 4]);
                al[mf][3] = __float_as_uint(AL[base + 8*AS_STRIDE + 4]);
            }
            #pragma unroll
            for (int nf = 0; nf < 4; nf++) {
                int bbase = (k8 + col4)*BS_STRIDE + wn*32 + nf*8 + row4;
                uint32_t bh[2], bl[2];
                bh[0] = __float_as_uint(BH[bbase]);
                bh[1] = __float_as_uint(BH[bbase + 4*BS_STRIDE]);
                bl[0] = __float_as_uint(BL[bbase]);
                bl[1] = __float_as_uint(BL[bbase + 4*BS_STRIDE]);
                #pragma unroll
                for (int mf = 0; mf < 4; mf++) {
                    mma_tf32(acc[mf][nf], ah[mf], bh);
                    mma_tf32(acc[mf][nf], ah[mf], bl);
                    mma_tf32(acc[mf][nf], al[mf], bh);
                }
            }
        }
    }

    // ---- epilogue ----
    #pragma unroll
    for (int mf = 0; mf < 4; mf++) {
        int mr = m0 + wm*64 + mf*16 + row4;
        #pragma unroll
        for (int nf = 0; nf < 4; nf++) {
            int nc = n0 + wn*32 + nf*8 + col4*2;
            if (mr < M)
                *(float2*)(Cb + (size_t)mr*HW + nc) = make_float2(acc[mf][nf][0], acc[mf][nf][1]);
            if (mr + 8 < M)
                *(float2*)(Cb + (size_t)(mr+8)*HW + nc) = make_float2(acc[mf][nf][2], acc[mf][nf][3]);
        }
    }
}

// ---------------- depthwise 7x7 pad 3 (per channel) ----------------
__global__ void dw7_kernel(const float* __restrict__ in, const float* __restrict__ w,
                           float* __restrict__ out) {
    int tx = threadIdx.x;          // w
    int h  = blockIdx.x;
    int bc = blockIdx.y;           // b*C + c
    int c  = bc & 63;
    const float* wp = w + c*49;
    const float* ip = in + (size_t)bc*HW;
    float acc = 0.f;
    #pragma unroll
    for (int kh = 0; kh < 7; kh++) {
        int y = h + kh - 3;
        if (y < 0 || y >= Hh) continue;
        #pragma unroll
        for (int kw = 0; kw < 7; kw++) {
            int x = tx + kw - 3;
            if (x < 0 || x >= Ww) continue;
            acc += wp[kh*7+kw] * ip[y*Ww + x];
        }
    }
    out[(size_t)bc*HW + h*Ww + tx] = acc;
}

// ---------------- convnext pointwise MLP + residual ----------------
__global__ __launch_bounds__(256) void convnext_pw_kernel(
        const float* __restrict__ xres, const float* __restrict__ t,
        const float* __restrict__ pw1,  const float* __restrict__ pw2,
        float* __restrict__ out) {
    __shared__ float s1[64][64];
    __shared__ float s2[64][64];
    int tid = threadIdx.x;
    size_t g = (size_t)blockIdx.x * 256 + tid;
    int b = (int)(g / HW);
    int p = (int)(g % HW);
    const float* tp = t + (size_t)b*Cc*HW + p;
    float xin[64];
    #pragma unroll
    for (int i = 0; i < 64; i++) xin[i] = tp[(size_t)i*HW];
    float acc[64];
    #pragma unroll
    for (int i = 0; i < 64; i++) acc[i] = 0.f;

    for (int chunk = 0; chunk < 2; chunk++) {
        __syncthreads();
        for (int i = tid; i < 4096; i += 256) (&s1[0][0])[i] = pw1[chunk*4096 + i];
        for (int i = tid; i < 4096; i += 256) {
            int c = i >> 6, mm = i & 63;
            s2[c][mm] = pw2[c*128 + chunk*64 + mm];
        }
        __syncthreads();
        for (int mm = 0; mm < 64; mm += 4) {
            float hv[4];
            #pragma unroll
            for (int j = 0; j < 4; j++) {
                float s = 0.f;
                #pragma unroll
                for (int i = 0; i < 64; i += 4) {
                    float4 wv = *(const float4*)&s1[mm+j][i];
                    s += wv.x*xin[i] + wv.y*xin[i+1] + wv.z*xin[i+2] + wv.w*xin[i+3];
                }
                hv[j] = fmaxf(s, 0.f);
            }
            #pragma unroll
            for (int c = 0; c < 64; c++) {
                float4 wv = *(const float4*)&s2[c][mm];
                acc[c] += wv.x*hv[0] + wv.y*hv[1] + wv.z*hv[2] + wv.w*hv[3];
            }
        }
    }
    const float* xp = xres + (size_t)b*Cc*HW + p;
    float* op = out + (size_t)b*Cc*HW + p;
    #pragma unroll
    for (int c = 0; c < 64; c++) op[(size_t)c*HW] = xp[(size_t)c*HW] + acc[c];
}

// ---------------- 1x1 conv 64->64 + bias + leaky(0.1) ----------------
__global__ __launch_bounds__(256) void conv1x1_64_kernel(
        const float* __restrict__ in, const float* __restrict__ wgt,
        const float* __restrict__ bias, float* __restrict__ out) {
    __shared__ float sw[4096];
    int tid = threadIdx.x;
    for (int i = tid; i < 4096; i += 256) sw[i] = wgt[i];
    __syncthreads();
    size_t g = (size_t)blockIdx.x * 256 + tid;
    int b = (int)(g / HW);
    int p = (int)(g % HW);
    const float* ip = in + (size_t)b*64*HW + p;
    float x[64];
    #pragma unroll
    for (int i = 0; i < 64; i++) x[i] = ip[(size_t)i*HW];
    float* op = out + (size_t)b*64*HW + p;
    for (int co = 0; co < 64; co++) {
        float s = bias[co];
        #pragma unroll
        for (int i = 0; i < 64; i += 4) {
            float4 wv = *(const float4*)&sw[co*64 + i];
            s += wv.x*x[i] + wv.y*x[i+1] + wv.z*x[i+2] + wv.w*x[i+3];
        }
        s = (s > 0.f) ? s : 0.1f*s;
        op[(size_t)co*HW] = s;
    }
}

// ---------------- 3x3 conv 64->64 pad1 + bias + leaky(0.1) ----------------
__global__ __launch_bounds__(128) void conv3x3_kernel(
        const float* __restrict__ in, const float* __restrict__ wgt,
        const float* __restrict__ bias, float* __restrict__ out) {
    int tx = threadIdx.x;        // w
    int h  = blockIdx.x;
    int b  = blockIdx.y;
    __shared__ float sIn[3][Ww];
    __shared__ float sW[576];    // sW[k*64 + co]
    float acc[64];
    #pragma unroll
    for (int i = 0; i < 64; i++) acc[i] = 0.f;
    const float* inb = in + (size_t)b*64*HW;

    for (int ci = 0; ci < 64; ci++) {
        __syncthreads();
        const float* ip = inb + (size_t)ci*HW;
        #pragma unroll
        for (int r = 0; r < 3; r++) {
            int y = h + r - 1;
            sIn[r][tx] = (y >= 0 && y < Hh) ? ip[y*Ww + tx] : 0.f;
        }
        for (int i = tx; i < 576; i += 128)
            sW[i] = wgt[(size_t)(i & 63)*576 + ci*9 + (i >> 6)];
        __syncthreads();
        float a[9];
        #pragma unroll
        for (int kh = 0; kh < 3; kh++) {
            a[kh*3+0] = (tx >= 1)      ? sIn[kh][tx-1] : 0.f;
            a[kh*3+1] =                   sIn[kh][tx];
            a[kh*3+2] = (tx < Ww-1)    ? sIn[kh][tx+1] : 0.f;
        }
        #pragma unroll
        for (int k = 0; k < 9; k++) {
            float av = a[k];
            #pragma unroll
            for (int c4 = 0; c4 < 16; c4++) {
                float4 wv = *(const float4*)&sW[k*64 + c4*4];
                acc[c4*4+0] += wv.x*av;
                acc[c4*4+1] += wv.y*av;
                acc[c4*4+2] += wv.z*av;
                acc[c4*4+3] += wv.w*av;
            }
        }
    }
    float* op = out + (size_t)b*64*HW + h*Ww + tx;
    #pragma unroll
    for (int co = 0; co < 64; co++) {
        float v = acc[co] + bias[co];
        v = (v > 0.f) ? v : 0.1f*v;
        op[(size_t)co*HW] = v;
    }
}

// ---------------- 1x1 conv 64->18 + bias, offsets = 8*tanh ----------------
__global__ __launch_bounds__(256) void off_final_kernel(
        const float* __restrict__ in, const float* __restrict__ wgt,
        const float* __restrict__ bias, float* __restrict__ out) {
    __shared__ float sw[18*64];
    int tid = threadIdx.x;
    for (int i = tid; i < 18*64; i += 256) sw[i] = wgt[i];
    __syncthreads();
    size_t g = (size_t)blockIdx.x * 256 + tid;
    int b = (int)(g / HW);
    int p = (int)(g % HW);
    const float* ip = in + (size_t)b*64*HW + p;
    float x[64];
    #pragma unroll
    for (int i = 0; i < 64; i++) x[i] = ip[(size_t)i*HW];
    float* op = out + (size_t)b*18*HW + p;
    for (int co = 0; co < 18; co++) {
        float s = bias[co];
        #pragma unroll
        for (int i = 0; i < 64; i += 4) {
            float4 wv = *(const float4*)&sw[co*64 + i];
            s += wv.x*x[i] + wv.y*x[i+1] + wv.z*x[i+2] + wv.w*x[i+3];
        }
        op[(size_t)co*HW] = 8.f * tanhf(s);
    }
}

// ---------------- deformable bilinear gather ----------------
__global__ __launch_bounds__(128) void deform_kernel(
        const float* __restrict__ x, const float* __restrict__ off,
        float* __restrict__ xb) {
    int tx = threadIdx.x;   // w
    int h  = blockIdx.x;
    int k  = blockIdx.y;
    int b  = blockIdx.z;
    int pix = h*Ww + tx;
    const float* ob = off + (size_t)b*18*HW;
    float dy = ob[(size_t)(2*k)*HW + pix];
    float dx = ob[(size_t)(2*k+1)*HW + pix];
    float py = (float)h + (float)(k/3 - 1) + dy;
    float px = (float)tx + (float)(k%3 - 1) + dx;
    float y0f = floorf(py), x0f = floorf(px);
    int y0 = (int)y0f, x0 = (int)x0f;
    float wy1 = py - y0f, wy0 = 1.f - wy1;
    float wx1 = px - x0f, wx0 = 1.f - wx1;
    bool vy0 = (y0 >= 0 && y0 < Hh), vy1 = (y0+1 >= 0 && y0+1 < Hh);
    bool vx0 = (x0 >= 0 && x0 < Ww), vx1 = (x0+1 >= 0 && x0+1 < Ww);
    int yc0 = min(max(y0, 0), Hh-1),   yc1 = min(max(y0+1, 0), Hh-1);
    int xc0 = min(max(x0, 0), Ww-1),   xc1 = min(max(x0+1, 0), Ww-1);
    float w00 = (vy0 && vx0) ? wy0*wx0 : 0.f;
    float w01 = (vy0 && vx1) ? wy0*wx1 : 0.f;
    float w10 = (vy1 && vx0) ? wy1*wx0 : 0.f;
    float w11 = (vy1 && vx1) ? wy1*wx1 : 0.f;
    int i00 = yc0*Ww + xc0, i01 = yc0*Ww + xc1;
    int i10 = yc1*Ww + xc0, i11 = yc1*Ww + xc1;
    const float* xbase = x + (size_t)b*Cc*HW;
    float* op = xb + ((size_t)b*CK + k)*HW + pix;
    #pragma unroll 4
    for (int c = 0; c < 64; c++) {
        const float* xp = xbase + (size_t)c*HW;
        float v = w00*xp[i00] + w01*xp[i01] + w10*xp[i10] + w11*xp[i11];
        op[(size_t)c*9*HW] = v;
    }
}

// ---------------- grouped 9x9 1x1 conv (per channel c), optional elemwise mul ----------------
__global__ __launch_bounds__(128) void grouped9_kernel(
        const float* __restrict__ in, const float* __restrict__ in2,
        const float* __restrict__ wgt, float* __restrict__ out) {
    int tx = threadIdx.x;
    int h  = blockIdx.x;
    int bc = blockIdx.y;        // b*64 + c
    int c  = bc & 63;
    size_t base = ((size_t)(bc >> 6)*CK + c*9)*HW + h*Ww + tx;
    float v[9];
    #pragma unroll
    for (int k = 0; k < 9; k++) {
        float t = in[base + (size_t)k*HW];
        if (in2) t *= in2[base + (size_t)k*HW];
        v[k] = t;
    }
    const float* wp = wgt + c*81;
    #pragma unroll
    for (int j = 0; j < 9; j++) {
        float s = 0.f;
        #pragma unroll
        for (int k = 0; k < 9; k++) s += __ldg(&wp[j*9+k]) * v[k];
        out[base + (size_t)j*HW] = s;
    }
}

// ---------------- depthwise 3x3 pad1 on CK channels + activation ----------------
__global__ __launch_bounds__(128) void dw3ck_kernel(
        const float* __restrict__ in, const float* __restrict__ wgt,
        float* __restrict__ out, int act) {
    int tx = threadIdx.x;
    int h  = blockIdx.x;
    int bc = blockIdx.y;        // b*576 + cc
    int cc = bc % CK;
    const float* ip = in + (size_t)bc*HW;
    const float* wp = wgt + cc*9;
    float acc = 0.f;
    #pragma unroll
    for (int kh = 0; kh < 3; kh++) {
        int y = h + kh - 1;
        if (y < 0 || y >= Hh) continue;
        #pragma unroll
        for (int kw = 0; kw < 3; kw++) {
            int xw = tx + kw - 1;
            if (xw < 0 || xw >= Ww) continue;
            acc += __ldg(&wp[kh*3+kw]) * ip[y*Ww + xw];
        }
    }
    if (act == 0) acc = fmaxf(acc, 0.f);
    else          acc = 1.f / (1.f + expf(-acc));
    out[(size_t)bc*HW + h*Ww + tx] = acc;
}

// ---------------- host orchestration ----------------
extern "C" void kernel_launch(void* const* d_in, const int* in_sizes, int n_in,
                              void* d_out, int out_size) {
    const float* x       = (const float*)d_in[0];
    const float* enc_dw  = (const float*)d_in[1];
    const float* enc_pw1 = (const float*)d_in[2];
    const float* enc_pw2 = (const float*)d_in[3];
    const float* dec_dw  = (const float*)d_in[4];
    const float* dec_pw1 = (const float*)d_in[5];
    const float* dec_pw2 = (const float*)d_in[6];
    const float* off_w1  = (const float*)d_in[7];
    const float* off_b1  = (const float*)d_in[8];
    const float* off_w2  = (const float*)d_in[9];
    const float* off_b2  = (const float*)d_in[10];
    const float* off_w3  = (const float*)d_in[11];
    const float* off_b3  = (const float*)d_in[12];
    const float* off_w4  = (const float*)d_in[13];
    const float* off_b4  = (const float*)d_in[14];
    const float* off_w5  = (const float*)d_in[15];
    const float* off_b5  = (const float*)d_in[16];
    const float* off_w6  = (const float*)d_in[17];
    const float* off_b6  = (const float*)d_in[18];
    const float* dct_w   = (const float*)d_in[19];
    const float* wie_w1  = (const float*)d_in[20];
    const float* wie_w2  = (const float*)d_in[21];
    const float* wie_w3  = (const float*)d_in[22];
    const float* wie_w4  = (const float*)d_in[23];
    const float* wie_w5  = (const float*)d_in[24];
    const float* wie_w6  = (const float*)d_in[25];
    const float* inv_w1  = (const float*)d_in[26];
    const float* inv_w2  = (const float*)d_in[27];

    float *xe, *t1, *bufA, *bufB, *offs, *xb, *dct, *y1, *y2;
    cudaGetSymbolAddress((void**)&xe,   g_xe);
    cudaGetSymbolAddress((void**)&t1,   g_t1);
    cudaGetSymbolAddress((void**)&bufA, g_bufA);
    cudaGetSymbolAddress((void**)&bufB, g_bufB);
    cudaGetSymbolAddress((void**)&offs, g_off);
    cudaGetSymbolAddress((void**)&xb,   g_xb);
    cudaGetSymbolAddress((void**)&dct,  g_dct);
    cudaGetSymbolAddress((void**)&y1,   g_y1);
    cudaGetSymbolAddress((void**)&y2,   g_y2);

    cudaFuncSetAttribute(gemm_mma_kernel, cudaFuncAttributeMaxDynamicSharedMemorySize, GEMM_SMEM);

    const int pixBlocks = (Bz*HW) / 256;          // 256

    // ---- encoder convnext ----
    dw7_kernel<<<dim3(Hh, Bz*Cc), Ww>>>(x, enc_dw, t1);
    convnext_pw_kernel<<<pixBlocks, 256>>>(x, t1, enc_pw1, enc_pw2, xe);

    // ---- offset CNN ----
    conv1x1_64_kernel<<<pixBlocks, 256>>>(xe, off_w1, off_b1, bufA);
    conv3x3_kernel<<<dim3(Hh, Bz), Ww>>>(bufA, off_w2, off_b2, bufB);
    conv3x3_kernel<<<dim3(Hh, Bz), Ww>>>(bufB, off_w3, off_b3, bufA);
    conv3x3_kernel<<<dim3(Hh, Bz), Ww>>>(bufA, off_w4, off_b4, bufB);
    conv3x3_kernel<<<dim3(Hh, Bz), Ww>>>(bufB, off_w5, off_b5, bufA);
    off_final_kernel<<<pixBlocks, 256>>>(bufA, off_w6, off_b6, offs);

    // ---- deformable neighbourhood ----
    deform_kernel<<<dim3(Hh, KK, Bz), Ww>>>(xe, offs, xb);

    // ---- dct branch (grouped 9x9) ----
    grouped9_kernel<<<dim3(Hh, Bz*Cc), Ww>>>(xb, nullptr, dct_w, dct);

    // ---- wiener branch: three 576x576 GEMMs (3xTF32 mma.sync) + depthwise 3x3 ----
    dim3 ggrid(HW/BNt, (CK + BMt - 1)/BMt, Bz);    // 128 x 5 x 4
    gemm_mma_kernel<<<ggrid, 256, GEMM_SMEM>>>(wie_w1, xb, y1, CK, CK);
    dw3ck_kernel<<<dim3(Hh, Bz*CK), Ww>>>(y1, wie_w2, y2, 0);
    gemm_mma_kernel<<<ggrid, 256, GEMM_SMEM>>>(wie_w3, y2, y1, CK, CK);
    dw3ck_kernel<<<dim3(Hh, Bz*CK), Ww>>>(y1, wie_w4, y2, 0);
    gemm_mma_kernel<<<ggrid, 256, GEMM_SMEM>>>(wie_w5, y2, y1, CK, CK);
    dw3ck_kernel<<<dim3(Hh, Bz*CK), Ww>>>(y1, wie_w6, y2, 1);   // sigmoid -> wiener

    // ---- inverse: (wiener*dct) -> grouped 9x9 -> 576->64 GEMM ----
    grouped9_kernel<<<dim3(Hh, Bz*Cc), Ww>>>(y2, dct, inv_w1, y1);
    gemm_mma_kernel<<<dim3(HW/BNt, 1, Bz), 256, GEMM_SMEM>>>(inv_w2, y1, t1, 64, CK);

    // ---- decoder convnext -> d_out ----
    dw7_kernel<<<dim3(Hh, Bz*Cc), Ww>>>(t1, dec_dw, bufA);
    convnext_pw_kernel<<<pixBlocks, 256>>>(t1, bufA, dec_pw1, dec_pw2, (float*)d_out);
}